// round 1
// baseline (speedup 1.0000x reference)
#include <cuda_runtime.h>
#include <cstdint>

typedef unsigned long long ull;

#define N_NODES 50000
#define DIM 128
#define NREL 16
#define NBASIS 10
#define KTOT (NBASIS*DIM + 2*DIM)   /* 1536: [u | x | x_time] */
#define DECAYR 0.1f

// ---------------- device scratch (static: no allocs allowed) ----------------
__device__ int g_is64;
__device__ unsigned g_tmax_bits;
__device__ unsigned g_tmin_bits;
__device__ float g_wsum;
__device__ int   g_cnt[N_NODES*NREL];                       // 3.2 MB
__device__ float g_agg[(size_t)N_NODES*NREL*DIM];           // 409.6 MB
__device__ float g_aggT[(size_t)N_NODES*DIM];               // 25.6 MB
__device__ float g_A[(size_t)N_NODES*KTOT];                 // 307 MB
__device__ float g_B[KTOT*DIM];                             // 0.78 MB

// ---------------- helpers ----------------
__device__ __forceinline__ int ld_index(const void* p, size_t pos, int is64) {
    // values fit in int32; for int64 little-endian read the low word
    return is64 ? ((const int2*)p)[pos].x : ((const int*)p)[pos];
}

__device__ __forceinline__ ull pack2(float x, float y) {
    ull r; asm("mov.b64 %0, {%1,%2};" : "=l"(r) : "f"(x), "f"(y)); return r;
}
__device__ __forceinline__ ull fma2(ull a, ull b, ull c) {
    ull d; asm("fma.rn.f32x2 %0, %1, %2, %3;" : "=l"(d) : "l"(a), "l"(b), "l"(c)); return d;
}
__device__ __forceinline__ void unpack2(ull v, float& x, float& y) {
    asm("mov.b64 {%0,%1}, %2;" : "=f"(x), "=f"(y) : "l"(v));
}

// ---------------- k0: detect index width + init scalars ----------------
__global__ void k_detect(const unsigned* w) {
    __shared__ int s_any;
    if (threadIdx.x == 0) s_any = 0;
    __syncthreads();
    unsigned a = 0;
    for (int i = threadIdx.x; i < 512; i += blockDim.x)
        a |= w[2*i + 1];   // high words if int64 (always 0), src values if int32
    if (a) atomicOr(&s_any, 1);
    __syncthreads();
    if (threadIdx.x == 0) {
        g_is64 = s_any ? 0 : 1;
        g_tmax_bits = 0u;
        g_tmin_bits = 0x7f7fffffu;
        g_wsum = 0.f;
    }
}

// ---------------- k1: zero scratch ----------------
__global__ void k_zero() {
    size_t i = (size_t)blockIdx.x*blockDim.x + threadIdx.x;
    size_t stride = (size_t)gridDim.x*blockDim.x;
    float4 z = make_float4(0.f,0.f,0.f,0.f);
    float4* pa = (float4*)g_agg;
    for (size_t j = i; j < (size_t)N_NODES*NREL*DIM/4; j += stride) pa[j] = z;
    float4* pt = (float4*)g_aggT;
    for (size_t j = i; j < (size_t)N_NODES*DIM/4; j += stride) pt[j] = z;
    int4* pc = (int4*)g_cnt;
    for (size_t j = i; j < (size_t)N_NODES*NREL/4; j += stride) pc[j] = make_int4(0,0,0,0);
}

// ---------------- k2: min/max of edge_time (nonneg -> uint-bit order) ----------------
__global__ void k_minmax(const float* __restrict__ t, int E) {
    float mx = 0.f, mn = 1e30f;     // safe inits: times in [0,1)
    for (int i = blockIdx.x*blockDim.x + threadIdx.x; i < E; i += gridDim.x*blockDim.x) {
        float v = t[i]; mx = fmaxf(mx, v); mn = fminf(mn, v);
    }
    for (int o = 16; o > 0; o >>= 1) {
        mx = fmaxf(mx, __shfl_xor_sync(0xffffffffu, mx, o));
        mn = fminf(mn, __shfl_xor_sync(0xffffffffu, mn, o));
    }
    if ((threadIdx.x & 31) == 0) {
        atomicMax(&g_tmax_bits, __float_as_uint(mx));
        atomicMin(&g_tmin_bits, __float_as_uint(mn));
    }
}

// ---------------- k3: sum of unnormalized decay weights ----------------
__global__ void k_wsum(const float* __restrict__ t, int E) {
    float tmax = __uint_as_float(g_tmax_bits);
    float tmin = __uint_as_float(g_tmin_bits);
    float inv = DECAYR / ((tmax - tmin) + 1e-8f);
    float s = 0.f;
    for (int i = blockIdx.x*blockDim.x + threadIdx.x; i < E; i += gridDim.x*blockDim.x)
        s += expf(-(tmax - t[i]) * inv);
    for (int o = 16; o > 0; o >>= 1) s += __shfl_xor_sync(0xffffffffu, s, o);
    if ((threadIdx.x & 31) == 0) atomicAdd(&g_wsum, s);
}

// ---------------- k4: edge scatter (one warp per edge) ----------------
__global__ void k_edge(const void* __restrict__ ei, const void* __restrict__ et,
                       const float* __restrict__ tim, const float* __restrict__ x, int E) {
    int gw = (blockIdx.x*blockDim.x + threadIdx.x) >> 5;
    int lane = threadIdx.x & 31;
    if (gw >= E) return;
    int is64 = g_is64;
    int src = 0, dst = 0, typ = 0;
    if (lane == 0) {
        src = ld_index(ei, (size_t)gw, is64);
        dst = ld_index(ei, (size_t)E + gw, is64);
        typ = ld_index(et, (size_t)gw, is64);
    }
    src = __shfl_sync(0xffffffffu, src, 0);
    dst = __shfl_sync(0xffffffffu, dst, 0);
    typ = __shfl_sync(0xffffffffu, typ, 0);

    float tmax = __uint_as_float(g_tmax_bits);
    float tmin = __uint_as_float(g_tmin_bits);
    float w = expf(-DECAYR * (tmax - tim[gw]) / ((tmax - tmin) + 1e-8f)) / (g_wsum + 1e-8f);

    float4 xv = ((const float4*)x)[(size_t)src*(DIM/4) + lane];

    float* pa = &g_agg[(size_t)(dst*NREL + typ)*DIM + lane*4];
    asm volatile("red.global.add.v4.f32 [%0], {%1,%2,%3,%4};"
                 :: "l"(pa), "f"(xv.x), "f"(xv.y), "f"(xv.z), "f"(xv.w) : "memory");
    float* pt = &g_aggT[(size_t)dst*DIM + lane*4];
    asm volatile("red.global.add.v4.f32 [%0], {%1,%2,%3,%4};"
                 :: "l"(pt), "f"(w*xv.x), "f"(w*xv.y), "f"(w*xv.z), "f"(w*xv.w) : "memory");
    if (lane == 0) atomicAdd(&g_cnt[dst*NREL + typ], 1);
}

// ---------------- k5: assemble B = [basis ; root ; tp_w] ----------------
__global__ void k_copyB(const float* __restrict__ basis, const float* __restrict__ root,
                        const float* __restrict__ tpw) {
    int i = blockIdx.x*blockDim.x + threadIdx.x;
    const int B0 = NBASIS*DIM*DIM;        // 163840
    const int B1 = B0 + DIM*DIM;          // 180224
    if (i < B0)              g_B[i] = basis[i];
    else if (i < B1)         g_B[i] = root[i - B0];
    else if (i < KTOT*DIM)   g_B[i] = tpw[i - B1];
}

// ---------------- k6: build A = [u | x | x_time] ----------------
__global__ void k_buildA(const float* __restrict__ x, const float* __restrict__ comp) {
    int n = blockIdx.x, i = threadIdx.x;
    __shared__ float s_comp[NREL*NBASIS];
    __shared__ int   s_cnt[NREL];
    for (int j = i; j < NREL*NBASIS; j += blockDim.x) s_comp[j] = comp[j];
    if (i < NREL) s_cnt[i] = g_cnt[n*NREL + i];
    __syncthreads();

    float u[NBASIS];
#pragma unroll
    for (int b = 0; b < NBASIS; b++) u[b] = 0.f;
    int deg = 0;
#pragma unroll
    for (int r = 0; r < NREL; r++) {
        int c = s_cnt[r]; deg += c;
        float a = g_agg[(size_t)(n*NREL + r)*DIM + i] * (1.f / (float)max(c, 1));
#pragma unroll
        for (int b = 0; b < NBASIS; b++) u[b] += s_comp[r*NBASIS + b] * a;
    }
    float* Ar = g_A + (size_t)n*KTOT;
#pragma unroll
    for (int b = 0; b < NBASIS; b++) Ar[b*DIM + i] = u[b];
    Ar[NBASIS*DIM + i] = x[(size_t)n*DIM + i];
    Ar[NBASIS*DIM + DIM + i] = g_aggT[(size_t)n*DIM + i] / (float)max(deg, 1);
}

// ---------------- k7: fused GEMM [N,1536]@[1536,128] + bias + relu + LayerNorm ----------------
__global__ void __launch_bounds__(256, 1)
k_gemm(const float* __restrict__ bias, const float* __restrict__ tpb,
       const float* __restrict__ gamma, const float* __restrict__ beta,
       float* __restrict__ out, int N) {
    __shared__ float As[16][128];
    __shared__ float Bs[16][128];
    const int tid = threadIdx.x;
    const int tx = tid & 15, ty = tid >> 4;
    const int row0 = blockIdx.x * 128;

    ull acc[8][4];
#pragma unroll
    for (int i = 0; i < 8; i++)
#pragma unroll
        for (int q = 0; q < 4; q++) acc[i][q] = 0ull;

    float cb[8], gv[8], bv[8];
#pragma unroll
    for (int q = 0; q < 4; q++) {
        int o = 2*tx + 32*q;
        cb[2*q]   = bias[o]   + tpb[o];
        cb[2*q+1] = bias[o+1] + tpb[o+1];
        gv[2*q] = gamma[o];   gv[2*q+1] = gamma[o+1];
        bv[2*q] = beta[o];    bv[2*q+1] = beta[o+1];
    }

    const int lm = tid >> 1, lk = (tid & 1) * 8;   // A-tile loader mapping
    const int bk = tid >> 4, bo = (tid & 15) * 8;  // B-tile loader mapping

    for (int kt = 0; kt < KTOT/16; kt++) {
        float4 v0, v1;
        int row = row0 + lm;
        if (row < N) {
            const float* p = g_A + (size_t)row*KTOT + kt*16 + lk;
            v0 = *(const float4*)p;  v1 = *(const float4*)(p + 4);
        } else {
            v0 = make_float4(0.f,0.f,0.f,0.f); v1 = v0;
        }
        As[lk+0][lm]=v0.x; As[lk+1][lm]=v0.y; As[lk+2][lm]=v0.z; As[lk+3][lm]=v0.w;
        As[lk+4][lm]=v1.x; As[lk+5][lm]=v1.y; As[lk+6][lm]=v1.z; As[lk+7][lm]=v1.w;

        const float* pb = g_B + (kt*16 + bk)*DIM + bo;
        *(float4*)&Bs[bk][bo]   = *(const float4*)pb;
        *(float4*)&Bs[bk][bo+4] = *(const float4*)(pb + 4);
        __syncthreads();

#pragma unroll
        for (int k = 0; k < 16; k++) {
            float4 a0 = *(const float4*)&As[k][ty*8];
            float4 a1 = *(const float4*)&As[k][ty*8 + 4];
            ull ad[8];
            ad[0]=pack2(a0.x,a0.x); ad[1]=pack2(a0.y,a0.y);
            ad[2]=pack2(a0.z,a0.z); ad[3]=pack2(a0.w,a0.w);
            ad[4]=pack2(a1.x,a1.x); ad[5]=pack2(a1.y,a1.y);
            ad[6]=pack2(a1.z,a1.z); ad[7]=pack2(a1.w,a1.w);
            ull bq[4];
#pragma unroll
            for (int q = 0; q < 4; q++) bq[q] = *(const ull*)&Bs[k][2*tx + 32*q];
#pragma unroll
            for (int i = 0; i < 8; i++)
#pragma unroll
                for (int q = 0; q < 4; q++) acc[i][q] = fma2(ad[i], bq[q], acc[i][q]);
        }
        __syncthreads();
    }

    // epilogue: +bias, relu, layernorm per row (row lives in 16 consecutive lanes)
#pragma unroll
    for (int i = 0; i < 8; i++) {
        float h[8];
        float s = 0.f, ss = 0.f;
#pragma unroll
        for (int q = 0; q < 4; q++) {
            float x0, x1; unpack2(acc[i][q], x0, x1);
            x0 = fmaxf(x0 + cb[2*q],   0.f);
            x1 = fmaxf(x1 + cb[2*q+1], 0.f);
            h[2*q] = x0; h[2*q+1] = x1;
            s += x0 + x1; ss += x0*x0 + x1*x1;
        }
#pragma unroll
        for (int m = 1; m < 16; m <<= 1) {
            s  += __shfl_xor_sync(0xffffffffu, s,  m);
            ss += __shfl_xor_sync(0xffffffffu, ss, m);
        }
        float mean = s * (1.f/128.f);
        float var  = ss * (1.f/128.f) - mean*mean;
        float rs = rsqrtf(var + 1e-5f);
        int row = row0 + ty*8 + i;
        if (row < N) {
            float* po = out + (size_t)row*DIM;
#pragma unroll
            for (int q = 0; q < 4; q++) {
                int o = 2*tx + 32*q;
                float2 v;
                v.x = (h[2*q]   - mean)*rs*gv[2*q]   + bv[2*q];
                v.y = (h[2*q+1] - mean)*rs*gv[2*q+1] + bv[2*q+1];
                *(float2*)(po + o) = v;
            }
        }
    }
}

// ---------------- launch ----------------
extern "C" void kernel_launch(void* const* d_in, const int* in_sizes, int n_in,
                              void* d_out, int out_size) {
    const float* x     = (const float*)d_in[0];
    const void*  ei    = d_in[1];
    const void*  et    = d_in[2];
    const float* tim   = (const float*)d_in[3];
    const float* basis = (const float*)d_in[4];
    const float* comp  = (const float*)d_in[5];
    const float* root  = (const float*)d_in[6];
    const float* bias  = (const float*)d_in[7];
    const float* tpw   = (const float*)d_in[8];
    const float* tpb   = (const float*)d_in[9];
    const float* gamma = (const float*)d_in[10];
    const float* beta  = (const float*)d_in[11];
    float* out = (float*)d_out;

    int E = in_sizes[3];            // edge_time element count
    int N = in_sizes[0] / DIM;

    k_detect<<<1, 256>>>((const unsigned*)ei);
    k_zero  <<<4096, 256>>>();
    k_minmax<<<1024, 256>>>(tim, E);
    k_wsum  <<<1024, 256>>>(tim, E);
    k_edge  <<<(E + 7)/8, 256>>>(ei, et, tim, x, E);
    k_copyB <<<(KTOT*DIM + 255)/256, 256>>>(basis, root, tpw);
    k_buildA<<<N, 128>>>(x, comp);
    k_gemm  <<<(N + 127)/128, 256>>>(bias, tpb, gamma, beta, out, N);
}

// round 2
// speedup vs baseline: 1.7379x; 1.7379x over previous
#include <cuda_runtime.h>
#include <cstdint>

typedef unsigned long long ull;

#define N_NODES 50000
#define DIM 128
#define NREL 16
#define NBASIS 10
#define AK (NBASIS*DIM + DIM)        /* 1408: [u | x_time] stored in g_A */
#define KTOT (NBASIS*DIM + 2*DIM)    /* 1536 logical K: [u | x | x_time] */
#define E_MAX 1600000
#define DECAYR 0.1f

// ---------------- device scratch (static: no allocs allowed) ----------------
__device__ int g_is64;
__device__ unsigned g_tmax_bits;
__device__ unsigned g_tmin_bits;
__device__ float g_wsum;
__device__ int   g_cnt[N_NODES*NREL];            // per-(node,rel) counts, 3.2 MB
__device__ int   g_rowloc[N_NODES];              // block-local exclusive scan
__device__ int   g_blk[64];                      // block sums
__device__ int   g_rowptr[N_NODES + 1];
__device__ int   g_cursor[N_NODES];
__device__ int   g_pack[E_MAX];                  // src | typ<<18
__device__ float g_w[E_MAX];                     // normalized decay weight
__device__ float g_A[(size_t)N_NODES*AK];        // 281 MB
__device__ float g_B[KTOT*DIM];                  // 786 KB

// ---------------- helpers ----------------
__device__ __forceinline__ int ld_index(const void* p, size_t pos, int is64) {
    return is64 ? ((const int2*)p)[pos].x : ((const int*)p)[pos];
}
__device__ __forceinline__ ull pack2(float x, float y) {
    ull r; asm("mov.b64 %0, {%1,%2};" : "=l"(r) : "f"(x), "f"(y)); return r;
}
__device__ __forceinline__ ull fma2(ull a, ull b, ull c) {
    ull d; asm("fma.rn.f32x2 %0, %1, %2, %3;" : "=l"(d) : "l"(a), "l"(b), "l"(c)); return d;
}
__device__ __forceinline__ void unpack2(ull v, float& x, float& y) {
    asm("mov.b64 {%0,%1}, %2;" : "=f"(x), "=f"(y) : "l"(v));
}

// ---------------- k0: detect index width + init scalars ----------------
__global__ void k_detect(const unsigned* w) {
    __shared__ int s_any;
    if (threadIdx.x == 0) s_any = 0;
    __syncthreads();
    unsigned a = 0;
    for (int i = threadIdx.x; i < 512; i += blockDim.x)
        a |= w[2*i + 1];
    if (a) atomicOr(&s_any, 1);
    __syncthreads();
    if (threadIdx.x == 0) {
        g_is64 = s_any ? 0 : 1;
        g_tmax_bits = 0u;
        g_tmin_bits = 0x7f7fffffu;
        g_wsum = 0.f;
    }
}

// ---------------- k1: zero counts ----------------
__global__ void k_zero_cnt() {
    int i = blockIdx.x*blockDim.x + threadIdx.x;
    if (i < N_NODES*NREL/4) ((int4*)g_cnt)[i] = make_int4(0,0,0,0);
}

// ---------------- k2: min/max of edge_time ----------------
__global__ void k_minmax(const float* __restrict__ t, int E) {
    float mx = 0.f, mn = 1e30f;
    for (int i = blockIdx.x*blockDim.x + threadIdx.x; i < E; i += gridDim.x*blockDim.x) {
        float v = t[i]; mx = fmaxf(mx, v); mn = fminf(mn, v);
    }
    for (int o = 16; o > 0; o >>= 1) {
        mx = fmaxf(mx, __shfl_xor_sync(0xffffffffu, mx, o));
        mn = fminf(mn, __shfl_xor_sync(0xffffffffu, mn, o));
    }
    if ((threadIdx.x & 31) == 0) {
        atomicMax(&g_tmax_bits, __float_as_uint(mx));
        atomicMin(&g_tmin_bits, __float_as_uint(mn));
    }
}

// ---------------- k3: sum of unnormalized decay weights ----------------
__global__ void k_wsum(const float* __restrict__ t, int E) {
    float tmax = __uint_as_float(g_tmax_bits);
    float tmin = __uint_as_float(g_tmin_bits);
    float inv = DECAYR / ((tmax - tmin) + 1e-8f);
    float s = 0.f;
    for (int i = blockIdx.x*blockDim.x + threadIdx.x; i < E; i += gridDim.x*blockDim.x)
        s += expf(-(tmax - t[i]) * inv);
    for (int o = 16; o > 0; o >>= 1) s += __shfl_xor_sync(0xffffffffu, s, o);
    if ((threadIdx.x & 31) == 0) atomicAdd(&g_wsum, s);
}

// ---------------- k4: per-(dst,rel) counts ----------------
__global__ void k_count(const void* __restrict__ ei, const void* __restrict__ et, int E) {
    int i = blockIdx.x*blockDim.x + threadIdx.x;
    if (i >= E) return;
    int is64 = g_is64;
    int dst = ld_index(ei, (size_t)E + i, is64);
    int typ = ld_index(et, (size_t)i, is64);
    atomicAdd(&g_cnt[dst*NREL + typ], 1);
}

// ---------------- k5: scan stage 1 (per-block exclusive scan of node degrees) ----
__global__ void k_scan1(int N) {
    int n = blockIdx.x*1024 + threadIdx.x;
    int lane = threadIdx.x & 31, warp = threadIdx.x >> 5;
    int deg = 0;
    if (n < N) {
        const int4* c = (const int4*)&g_cnt[n*NREL];
        int4 a = c[0], b = c[1], d = c[2], e = c[3];
        deg = a.x+a.y+a.z+a.w + b.x+b.y+b.z+b.w + d.x+d.y+d.z+d.w + e.x+e.y+e.z+e.w;
    }
    int v = deg;
    for (int o = 1; o < 32; o <<= 1) {
        int t = __shfl_up_sync(0xffffffffu, v, o);
        if (lane >= o) v += t;
    }
    __shared__ int ws[32];
    if (lane == 31) ws[warp] = v;
    __syncthreads();
    if (warp == 0) {
        int t = ws[lane];
        for (int o = 1; o < 32; o <<= 1) {
            int u = __shfl_up_sync(0xffffffffu, t, o);
            if (lane >= o) t += u;
        }
        ws[lane] = t;
    }
    __syncthreads();
    int add = (warp > 0) ? ws[warp-1] : 0;
    int incl = v + add;
    if (n < N) g_rowloc[n] = incl - deg;
    if (threadIdx.x == 1023) g_blk[blockIdx.x] = incl;
}

// ---------------- k6: scan stage 2 (serial over block sums) ----------------
__global__ void k_scan2(int nblk) {
    if (threadIdx.x == 0) {
        int s = 0;
        for (int i = 0; i < nblk; i++) { int v = g_blk[i]; g_blk[i] = s; s += v; }
    }
}

// ---------------- k7: scan stage 3 (finalize rowptr + cursors) ----------------
__global__ void k_scan3(int N, int E) {
    int n = blockIdx.x*blockDim.x + threadIdx.x;
    if (n < N) {
        int v = g_rowloc[n] + g_blk[n >> 10];
        g_rowptr[n] = v;
        g_cursor[n] = v;
    }
    if (n == 0) g_rowptr[N] = E;
}

// ---------------- k8: scatter edges into CSR ----------------
__global__ void k_scatter(const void* __restrict__ ei, const void* __restrict__ et,
                          const float* __restrict__ tim, int E) {
    int i = blockIdx.x*blockDim.x + threadIdx.x;
    if (i >= E) return;
    int is64 = g_is64;
    int src = ld_index(ei, (size_t)i, is64);
    int dst = ld_index(ei, (size_t)E + i, is64);
    int typ = ld_index(et, (size_t)i, is64);
    float tmax = __uint_as_float(g_tmax_bits);
    float tmin = __uint_as_float(g_tmin_bits);
    float w = expf(-DECAYR * (tmax - tim[i]) / ((tmax - tmin) + 1e-8f)) / (g_wsum + 1e-8f);
    int pos = atomicAdd(&g_cursor[dst], 1);
    g_pack[pos] = src | (typ << 18);
    g_w[pos] = w;
}

// ---------------- k9: assemble B = [basis ; root ; tp_w] ----------------
__global__ void k_copyB(const float* __restrict__ basis, const float* __restrict__ root,
                        const float* __restrict__ tpw) {
    int i = blockIdx.x*blockDim.x + threadIdx.x;
    const int B0 = NBASIS*DIM*DIM;        // 163840
    const int B1 = B0 + DIM*DIM;          // 180224
    if (i < B0)              g_B[i] = basis[i];
    else if (i < B1)         g_B[i] = root[i - B0];
    else if (i < KTOT*DIM)   g_B[i] = tpw[i - B1];
}

// ---------------- k10: per-node reduce (one warp per node) ----------------
__global__ void __launch_bounds__(256)
k_node(const float* __restrict__ x, const float* __restrict__ comp, int N) {
    __shared__ ull s_coef[8][NREL*NBASIS];   // pre-duplicated f32x2 coefs, 10 KB
    int lane = threadIdx.x & 31;
    int wib  = threadIdx.x >> 5;
    int n = (blockIdx.x << 3) + wib;
    if (n >= N) return;

    // coef[r][b] = comp[r][b] / max(cnt[n,r],1), duplicated into both f32x2 halves
    for (int j = lane; j < NREL*NBASIS; j += 32) {
        int r = j / NBASIS;
        int c = g_cnt[n*NREL + r];
        float v = comp[j] / (float)max(c, 1);
        s_coef[wib][j] = pack2(v, v);
    }
    __syncwarp();

    int s = g_rowptr[n], e = g_rowptr[n+1];

    ull u[NBASIS][2];
#pragma unroll
    for (int b = 0; b < NBASIS; b++) { u[b][0] = 0ull; u[b][1] = 0ull; }
    ull at0 = 0ull, at1 = 0ull;

    const float4* x4 = (const float4*)x;
    for (int i = s; i < e; i++) {
        int pk  = __ldg(&g_pack[i]);          // broadcast load
        float w = __ldg(&g_w[i]);
        int src = pk & 0x3ffff;
        int typ = pk >> 18;
        float4 xv = x4[(size_t)src*(DIM/4) + lane];
        ull x01 = pack2(xv.x, xv.y);
        ull x23 = pack2(xv.z, xv.w);
        ull wp  = pack2(w, w);
        at0 = fma2(wp, x01, at0);
        at1 = fma2(wp, x23, at1);
        const ull* cf = &s_coef[wib][typ*NBASIS];
#pragma unroll
        for (int b = 0; b < NBASIS; b++) {
            ull cp = cf[b];
            u[b][0] = fma2(cp, x01, u[b][0]);
            u[b][1] = fma2(cp, x23, u[b][1]);
        }
    }

    float* Ar = g_A + (size_t)n*AK;
#pragma unroll
    for (int b = 0; b < NBASIS; b++) {
        float f0, f1, f2, f3;
        unpack2(u[b][0], f0, f1);
        unpack2(u[b][1], f2, f3);
        *(float4*)(Ar + b*DIM + lane*4) = make_float4(f0, f1, f2, f3);
    }
    float invd = 1.f / (float)max(e - s, 1);
    float t0, t1, t2, t3;
    unpack2(at0, t0, t1);
    unpack2(at1, t2, t3);
    *(float4*)(Ar + NBASIS*DIM + lane*4) =
        make_float4(t0*invd, t1*invd, t2*invd, t3*invd);
}

// ---------------- k11: fused GEMM [N,1536]@[1536,128] + bias + relu + LayerNorm ----
__global__ void __launch_bounds__(256, 2)
k_gemm(const float* __restrict__ x,
       const float* __restrict__ bias, const float* __restrict__ tpb,
       const float* __restrict__ gamma, const float* __restrict__ beta,
       float* __restrict__ out, int N) {
    __shared__ float As[16][128];
    __shared__ float Bs[16][128];
    const int tid = threadIdx.x;
    const int tx = tid & 15, ty = tid >> 4;
    const int row0 = blockIdx.x * 128;

    ull acc[8][4];
#pragma unroll
    for (int i = 0; i < 8; i++)
#pragma unroll
        for (int q = 0; q < 4; q++) acc[i][q] = 0ull;

    float cb[8], gv[8], bv[8];
#pragma unroll
    for (int q = 0; q < 4; q++) {
        int o = 2*tx + 32*q;
        cb[2*q]   = bias[o]   + tpb[o];
        cb[2*q+1] = bias[o+1] + tpb[o+1];
        gv[2*q] = gamma[o];   gv[2*q+1] = gamma[o+1];
        bv[2*q] = beta[o];    bv[2*q+1] = beta[o+1];
    }

    const int lm = tid >> 1, lk = (tid & 1) * 8;   // A-tile loader mapping
    const int bk = tid >> 4, bo = (tid & 15) * 8;  // B-tile loader mapping

    for (int kt = 0; kt < KTOT/16; kt++) {
        float4 v0, v1;
        int row = row0 + lm;
        int kc = kt*16 + lk;   // logical K column of first loaded element
        if (row < N) {
            const float* p;
            if (kc < NBASIS*DIM)              p = g_A + (size_t)row*AK + kc;
            else if (kc < NBASIS*DIM + DIM)   p = x + (size_t)row*DIM + (kc - NBASIS*DIM);
            else                              p = g_A + (size_t)row*AK + (kc - DIM);
            v0 = *(const float4*)p;  v1 = *(const float4*)(p + 4);
        } else {
            v0 = make_float4(0.f,0.f,0.f,0.f); v1 = v0;
        }
        As[lk+0][lm]=v0.x; As[lk+1][lm]=v0.y; As[lk+2][lm]=v0.z; As[lk+3][lm]=v0.w;
        As[lk+4][lm]=v1.x; As[lk+5][lm]=v1.y; As[lk+6][lm]=v1.z; As[lk+7][lm]=v1.w;

        const float* pb = g_B + (kt*16 + bk)*DIM + bo;
        *(float4*)&Bs[bk][bo]   = *(const float4*)pb;
        *(float4*)&Bs[bk][bo+4] = *(const float4*)(pb + 4);
        __syncthreads();

#pragma unroll
        for (int k = 0; k < 16; k++) {
            float4 a0 = *(const float4*)&As[k][ty*8];
            float4 a1 = *(const float4*)&As[k][ty*8 + 4];
            ull ad[8];
            ad[0]=pack2(a0.x,a0.x); ad[1]=pack2(a0.y,a0.y);
            ad[2]=pack2(a0.z,a0.z); ad[3]=pack2(a0.w,a0.w);
            ad[4]=pack2(a1.x,a1.x); ad[5]=pack2(a1.y,a1.y);
            ad[6]=pack2(a1.z,a1.z); ad[7]=pack2(a1.w,a1.w);
            ull bq[4];
#pragma unroll
            for (int q = 0; q < 4; q++) bq[q] = *(const ull*)&Bs[k][2*tx + 32*q];
#pragma unroll
            for (int i = 0; i < 8; i++)
#pragma unroll
                for (int q = 0; q < 4; q++) acc[i][q] = fma2(ad[i], bq[q], acc[i][q]);
        }
        __syncthreads();
    }

    // epilogue: +bias, relu, layernorm per row (row lives in 16 consecutive lanes)
#pragma unroll
    for (int i = 0; i < 8; i++) {
        float h[8];
        float s = 0.f, ss = 0.f;
#pragma unroll
        for (int q = 0; q < 4; q++) {
            float x0, x1; unpack2(acc[i][q], x0, x1);
            x0 = fmaxf(x0 + cb[2*q],   0.f);
            x1 = fmaxf(x1 + cb[2*q+1], 0.f);
            h[2*q] = x0; h[2*q+1] = x1;
            s += x0 + x1; ss += x0*x0 + x1*x1;
        }
#pragma unroll
        for (int m = 1; m < 16; m <<= 1) {
            s  += __shfl_xor_sync(0xffffffffu, s,  m);
            ss += __shfl_xor_sync(0xffffffffu, ss, m);
        }
        float mean = s * (1.f/128.f);
        float var  = ss * (1.f/128.f) - mean*mean;
        float rs = rsqrtf(var + 1e-5f);
        int row = row0 + ty*8 + i;
        if (row < N) {
            float* po = out + (size_t)row*DIM;
#pragma unroll
            for (int q = 0; q < 4; q++) {
                int o = 2*tx + 32*q;
                float2 v;
                v.x = (h[2*q]   - mean)*rs*gv[2*q]   + bv[2*q];
                v.y = (h[2*q+1] - mean)*rs*gv[2*q+1] + bv[2*q+1];
                *(float2*)(po + o) = v;
            }
        }
    }
}

// ---------------- launch ----------------
extern "C" void kernel_launch(void* const* d_in, const int* in_sizes, int n_in,
                              void* d_out, int out_size) {
    const float* x     = (const float*)d_in[0];
    const void*  ei    = d_in[1];
    const void*  et    = d_in[2];
    const float* tim   = (const float*)d_in[3];
    const float* basis = (const float*)d_in[4];
    const float* comp  = (const float*)d_in[5];
    const float* root  = (const float*)d_in[6];
    const float* bias  = (const float*)d_in[7];
    const float* tpw   = (const float*)d_in[8];
    const float* tpb   = (const float*)d_in[9];
    const float* gamma = (const float*)d_in[10];
    const float* beta  = (const float*)d_in[11];
    float* out = (float*)d_out;

    int E = in_sizes[3];
    int N = in_sizes[0] / DIM;
    int nblk = (N + 1023) / 1024;

    k_detect  <<<1, 256>>>((const unsigned*)ei);
    k_zero_cnt<<<(N_NODES*NREL/4 + 255)/256, 256>>>();
    k_minmax  <<<1024, 256>>>(tim, E);
    k_wsum    <<<1024, 256>>>(tim, E);
    k_count   <<<(E + 255)/256, 256>>>(ei, et, E);
    k_scan1   <<<nblk, 1024>>>(N);
    k_scan2   <<<1, 32>>>(nblk);
    k_scan3   <<<(N + 255)/256, 256>>>(N, E);
    k_scatter <<<(E + 255)/256, 256>>>(ei, et, tim, E);
    k_copyB   <<<(KTOT*DIM + 255)/256, 256>>>(basis, root, tpw);
    k_node    <<<(N + 7)/8, 256>>>(x, comp, N);
    k_gemm    <<<(N + 127)/128, 256>>>(x, bias, tpb, gamma, beta, out, N);
}

// round 11
// speedup vs baseline: 2.0928x; 1.2042x over previous
#include <cuda_runtime.h>
#include <cuda_bf16.h>
#include <cstdint>

typedef unsigned long long ull;
typedef unsigned short ushort_t;

#define N_NODES 50000
#define DIM 128
#define NREL 16
#define NBASIS 10
#define KTOT (NBASIS*DIM + 2*DIM)    /* 1536: [u | x | x_time] */
#define E_MAX 1600000
#define DECAYR 0.1f
#define NCK 48                       /* K chunks of 32 */

// ---------------- device scratch (static: no allocs allowed) ----------------
__device__ int g_is64;
__device__ unsigned g_tmax_bits;
__device__ unsigned g_tmin_bits;
__device__ float g_wsum;
__device__ int   g_cnt[N_NODES*NREL];
__device__ int   g_rowloc[N_NODES];
__device__ int   g_blk[64];
__device__ int   g_rowptr[N_NODES + 1];
__device__ int   g_cursor[N_NODES];
__device__ int   g_pack[E_MAX];
__device__ float g_w[E_MAX];
__device__ ushort_t g_Ah[(size_t)N_NODES*KTOT];   // bf16 hi, 153.6 MB
__device__ ushort_t g_Al[(size_t)N_NODES*KTOT];   // bf16 lo, 153.6 MB
__device__ ushort_t g_Bth[DIM*KTOT];              // B^T hi [128 n][1536 k]
__device__ ushort_t g_Btl[DIM*KTOT];              // B^T lo

// ---------------- helpers ----------------
__device__ __forceinline__ int ld_index(const void* p, size_t pos, int is64) {
    return is64 ? ((const int2*)p)[pos].x : ((const int*)p)[pos];
}
__device__ __forceinline__ ull pack2(float x, float y) {
    ull r; asm("mov.b64 %0, {%1,%2};" : "=l"(r) : "f"(x), "f"(y)); return r;
}
__device__ __forceinline__ ull fma2(ull a, ull b, ull c) {
    ull d; asm("fma.rn.f32x2 %0, %1, %2, %3;" : "=l"(d) : "l"(a), "l"(b), "l"(c)); return d;
}
__device__ __forceinline__ void unpack2(ull v, float& x, float& y) {
    asm("mov.b64 {%0,%1}, %2;" : "=f"(x), "=f"(y) : "l"(v));
}
__device__ __forceinline__ void cvt_hl(float v, unsigned& h, unsigned& l) {
    __nv_bfloat16 hb = __float2bfloat16(v);
    float r = v - __bfloat162float(hb);
    __nv_bfloat16 lb = __float2bfloat16(r);
    h = (unsigned)__bfloat16_as_ushort(hb);
    l = (unsigned)__bfloat16_as_ushort(lb);
}
__device__ __forceinline__ void st4_hl(ushort_t* Hp, ushort_t* Lp, float4 v) {
    unsigned h0,l0,h1,l1,h2,l2,h3,l3;
    cvt_hl(v.x,h0,l0); cvt_hl(v.y,h1,l1); cvt_hl(v.z,h2,l2); cvt_hl(v.w,h3,l3);
    *(uint2*)Hp = make_uint2(h0 | (h1<<16), h2 | (h3<<16));
    *(uint2*)Lp = make_uint2(l0 | (l1<<16), l2 | (l3<<16));
}
__device__ __forceinline__ uint32_t smem_u32(const void* p) {
    uint32_t a;
    asm("{ .reg .u64 t; cvta.to.shared.u64 t, %1; cvt.u32.u64 %0, t; }" : "=r"(a) : "l"(p));
    return a;
}
__device__ __forceinline__ void ldm4(uint32_t* r, uint32_t addr) {
    asm volatile("ldmatrix.sync.aligned.m8n8.x4.shared.b16 {%0,%1,%2,%3}, [%4];"
                 : "=r"(r[0]),"=r"(r[1]),"=r"(r[2]),"=r"(r[3]) : "r"(addr));
}
__device__ __forceinline__ void mma16816(float* c, const uint32_t* a, const uint32_t* b) {
    asm volatile("mma.sync.aligned.m16n8k16.row.col.f32.bf16.bf16.f32 "
                 "{%0,%1,%2,%3}, {%4,%5,%6,%7}, {%8,%9}, {%0,%1,%2,%3};"
                 : "+f"(c[0]),"+f"(c[1]),"+f"(c[2]),"+f"(c[3])
                 : "r"(a[0]),"r"(a[1]),"r"(a[2]),"r"(a[3]), "r"(b[0]),"r"(b[1]));
}

// ---------------- k0: detect index width + init scalars ----------------
__global__ void k_detect(const unsigned* w) {
    __shared__ int s_any;
    if (threadIdx.x == 0) s_any = 0;
    __syncthreads();
    unsigned a = 0;
    for (int i = threadIdx.x; i < 512; i += blockDim.x) a |= w[2*i + 1];
    if (a) atomicOr(&s_any, 1);
    __syncthreads();
    if (threadIdx.x == 0) {
        g_is64 = s_any ? 0 : 1;
        g_tmax_bits = 0u;
        g_tmin_bits = 0x7f7fffffu;
        g_wsum = 0.f;
    }
}

// ---------------- k1: zero counts ----------------
__global__ void k_zero_cnt() {
    int i = blockIdx.x*blockDim.x + threadIdx.x;
    if (i < N_NODES*NREL/4) ((int4*)g_cnt)[i] = make_int4(0,0,0,0);
}

// ---------------- k2: min/max of edge_time ----------------
__global__ void k_minmax(const float* __restrict__ t, int E) {
    float mx = 0.f, mn = 1e30f;
    for (int i = blockIdx.x*blockDim.x + threadIdx.x; i < E; i += gridDim.x*blockDim.x) {
        float v = t[i]; mx = fmaxf(mx, v); mn = fminf(mn, v);
    }
    for (int o = 16; o > 0; o >>= 1) {
        mx = fmaxf(mx, __shfl_xor_sync(0xffffffffu, mx, o));
        mn = fminf(mn, __shfl_xor_sync(0xffffffffu, mn, o));
    }
    if ((threadIdx.x & 31) == 0) {
        atomicMax(&g_tmax_bits, __float_as_uint(mx));
        atomicMin(&g_tmin_bits, __float_as_uint(mn));
    }
}

// ---------------- k3: sum of unnormalized decay weights ----------------
__global__ void k_wsum(const float* __restrict__ t, int E) {
    float tmax = __uint_as_float(g_tmax_bits);
    float tmin = __uint_as_float(g_tmin_bits);
    float inv = DECAYR / ((tmax - tmin) + 1e-8f);
    float s = 0.f;
    for (int i = blockIdx.x*blockDim.x + threadIdx.x; i < E; i += gridDim.x*blockDim.x)
        s += expf(-(tmax - t[i]) * inv);
    for (int o = 16; o > 0; o >>= 1) s += __shfl_xor_sync(0xffffffffu, s, o);
    if ((threadIdx.x & 31) == 0) atomicAdd(&g_wsum, s);
}

// ---------------- k4: per-(dst,rel) counts ----------------
__global__ void k_count(const void* __restrict__ ei, const void* __restrict__ et, int E) {
    int i = blockIdx.x*blockDim.x + threadIdx.x;
    if (i >= E) return;
    int is64 = g_is64;
    int dst = ld_index(ei, (size_t)E + i, is64);
    int typ = ld_index(et, (size_t)i, is64);
    atomicAdd(&g_cnt[dst*NREL + typ], 1);
}

// ---------------- k5-7: degree scan ----------------
__global__ void k_scan1(int N) {
    int n = blockIdx.x*1024 + threadIdx.x;
    int lane = threadIdx.x & 31, warp = threadIdx.x >> 5;
    int deg = 0;
    if (n < N) {
        const int4* c = (const int4*)&g_cnt[n*NREL];
        int4 a = c[0], b = c[1], d = c[2], e = c[3];
        deg = a.x+a.y+a.z+a.w + b.x+b.y+b.z+b.w + d.x+d.y+d.z+d.w + e.x+e.y+e.z+e.w;
    }
    int v = deg;
    for (int o = 1; o < 32; o <<= 1) {
        int t = __shfl_up_sync(0xffffffffu, v, o);
        if (lane >= o) v += t;
    }
    __shared__ int ws[32];
    if (lane == 31) ws[warp] = v;
    __syncthreads();
    if (warp == 0) {
        int t = ws[lane];
        for (int o = 1; o < 32; o <<= 1) {
            int u = __shfl_up_sync(0xffffffffu, t, o);
            if (lane >= o) t += u;
        }
        ws[lane] = t;
    }
    __syncthreads();
    int add = (warp > 0) ? ws[warp-1] : 0;
    int incl = v + add;
    if (n < N) g_rowloc[n] = incl - deg;
    if (threadIdx.x == 1023) g_blk[blockIdx.x] = incl;
}
__global__ void k_scan2(int nblk) {
    if (threadIdx.x == 0) {
        int s = 0;
        for (int i = 0; i < nblk; i++) { int v = g_blk[i]; g_blk[i] = s; s += v; }
    }
}
__global__ void k_scan3(int N, int E) {
    int n = blockIdx.x*blockDim.x + threadIdx.x;
    if (n < N) {
        int v = g_rowloc[n] + g_blk[n >> 10];
        g_rowptr[n] = v;
        g_cursor[n] = v;
    }
    if (n == 0) g_rowptr[N] = E;
}

// ---------------- k8: scatter edges into CSR ----------------
__global__ void k_scatter(const void* __restrict__ ei, const void* __restrict__ et,
                          const float* __restrict__ tim, int E) {
    int i = blockIdx.x*blockDim.x + threadIdx.x;
    if (i >= E) return;
    int is64 = g_is64;
    int src = ld_index(ei, (size_t)i, is64);
    int dst = ld_index(ei, (size_t)E + i, is64);
    int typ = ld_index(et, (size_t)i, is64);
    float tmax = __uint_as_float(g_tmax_bits);
    float tmin = __uint_as_float(g_tmin_bits);
    float w = expf(-DECAYR * (tmax - tim[i]) / ((tmax - tmin) + 1e-8f)) / (g_wsum + 1e-8f);
    int pos = atomicAdd(&g_cursor[dst], 1);
    g_pack[pos] = src | (typ << 18);
    g_w[pos] = w;
}

// ---------------- k9: B^T hi/lo [128,1536] from basis/root/tp_w ----------------
__global__ void k_makeBt(const float* __restrict__ basis, const float* __restrict__ root,
                         const float* __restrict__ tpw) {
    int k = blockIdx.x*blockDim.x + threadIdx.x;   // 0..1535
    int n = blockIdx.y;                            // 0..127 (output col)
    if (k >= KTOT) return;
    float v;
    if (k < NBASIS*DIM)          v = basis[(size_t)(k>>7)*DIM*DIM + (k&127)*DIM + n];
    else if (k < NBASIS*DIM+DIM) v = root[(k - NBASIS*DIM)*DIM + n];
    else                         v = tpw[(k - NBASIS*DIM - DIM)*DIM + n];
    unsigned h, l;
    cvt_hl(v, h, l);
    g_Bth[n*KTOT + k] = (ushort_t)h;
    g_Btl[n*KTOT + k] = (ushort_t)l;
}

// ---------------- k10: per-node reduce -> A hi/lo (one warp per node) -----------
__global__ void __launch_bounds__(256)
k_node(const float* __restrict__ x, const float* __restrict__ comp, int N) {
    __shared__ ull s_coef[8][NREL*NBASIS];
    int lane = threadIdx.x & 31;
    int wib  = threadIdx.x >> 5;
    int n = (blockIdx.x << 3) + wib;
    if (n >= N) return;

    for (int j = lane; j < NREL*NBASIS; j += 32) {
        int r = j / NBASIS;
        int c = g_cnt[n*NREL + r];
        float v = comp[j] / (float)max(c, 1);
        s_coef[wib][j] = pack2(v, v);
    }
    __syncwarp();

    int s = g_rowptr[n], e = g_rowptr[n+1];

    ull u[NBASIS][2];
#pragma unroll
    for (int b = 0; b < NBASIS; b++) { u[b][0] = 0ull; u[b][1] = 0ull; }
    ull at0 = 0ull, at1 = 0ull;

    const float4* x4 = (const float4*)x;
    for (int i = s; i < e; i++) {
        int pk  = __ldg(&g_pack[i]);
        float w = __ldg(&g_w[i]);
        int src = pk & 0x3ffff;
        int typ = pk >> 18;
        float4 xv = x4[(size_t)src*(DIM/4) + lane];
        ull x01 = pack2(xv.x, xv.y);
        ull x23 = pack2(xv.z, xv.w);
        ull wp  = pack2(w, w);
        at0 = fma2(wp, x01, at0);
        at1 = fma2(wp, x23, at1);
        const ull* cf = &s_coef[wib][typ*NBASIS];
#pragma unroll
        for (int b = 0; b < NBASIS; b++) {
            ull cp = cf[b];
            u[b][0] = fma2(cp, x01, u[b][0]);
            u[b][1] = fma2(cp, x23, u[b][1]);
        }
    }

    size_t rowoff = (size_t)n*KTOT;
#pragma unroll
    for (int b = 0; b < NBASIS; b++) {
        float f0, f1, f2, f3;
        unpack2(u[b][0], f0, f1);
        unpack2(u[b][1], f2, f3);
        int c = b*DIM + lane*4;
        st4_hl(g_Ah + rowoff + c, g_Al + rowoff + c, make_float4(f0,f1,f2,f3));
    }
    float4 xn = x4[(size_t)n*(DIM/4) + lane];
    int cx = NBASIS*DIM + lane*4;
    st4_hl(g_Ah + rowoff + cx, g_Al + rowoff + cx, xn);
    float invd = 1.f / (float)max(e - s, 1);
    float t0, t1, t2, t3;
    unpack2(at0, t0, t1);
    unpack2(at1, t2, t3);
    int ct = NBASIS*DIM + DIM + lane*4;
    st4_hl(g_Ah + rowoff + ct, g_Al + rowoff + ct,
           make_float4(t0*invd, t1*invd, t2*invd, t3*invd));
}

// ---------------- k11: HMMA GEMM (static smem) + bias + relu + LayerNorm -------
// 128x128 CTA tile, K chunks of 32, single-buffered static SMEM (46.5 KB).
// 8 warps: wm = wid>>2 (2 x 64 rows), wn = wid&3 (4 x 32 cols).
// hi/lo bf16 split, 3 HMMA passes: Ah*Bh + Ah*Bl + Al*Bh, fp32 accum.
#define SROW 40   /* ushorts per smem row = 80 bytes (16B-aligned, conflict-free) */

__global__ void __launch_bounds__(256, 2)
k_gemm_hmma(const float* __restrict__ bias, const float* __restrict__ tpb,
            const float* __restrict__ gamma, const float* __restrict__ beta,
            float* __restrict__ out, int N) {
    __shared__ __align__(16) ushort_t sAh[128][SROW];
    __shared__ __align__(16) ushort_t sAl[128][SROW];
    __shared__ __align__(16) ushort_t sBh[128][SROW];
    __shared__ __align__(16) ushort_t sBl[128][SROW];
    __shared__ float  sCb[128], sGv[128], sBv[128];
    __shared__ float2 sPart[128][4];

    const int tid = threadIdx.x;
    const int wid = tid >> 5, lane = tid & 31;
    const int wm = wid >> 2, wn = wid & 3;
    const int row0 = blockIdx.x * 128;

    if (tid < 128) {
        sCb[tid] = bias[tid] + tpb[tid];
        sGv[tid] = gamma[tid];
        sBv[tid] = beta[tid];
    }

    float acc[4][4][4];
#pragma unroll
    for (int mt = 0; mt < 4; mt++)
#pragma unroll
        for (int nt = 0; nt < 4; nt++)
#pragma unroll
            for (int i = 0; i < 4; i++) acc[mt][nt][i] = 0.f;

    const uint32_t aH = smem_u32(sAh), aL = smem_u32(sAl);
    const uint32_t bH = smem_u32(sBh), bL = smem_u32(sBl);

    const int lrow = tid >> 1;           // loader row 0..127
    const int gr = row0 + lrow;
    const bool rvalid = (gr < N);
    const size_t abase = (size_t)(rvalid ? gr : 0) * KTOT;
    const size_t bbase = (size_t)lrow * KTOT;

    for (int c = 0; c < NCK; c++) {
        __syncthreads();   // protect smem reuse from previous compute
        {
            const uint4 z = make_uint4(0u,0u,0u,0u);
#pragma unroll
            for (int it = 0; it < 2; it++) {
                int seg = (tid & 1)*2 + it;          // 0..3
                int eoff = c*32 + seg*8;             // element offset in K
                uint4 vh = z, vl = z;
                if (rvalid) {
                    vh = *(const uint4*)(g_Ah + abase + eoff);
                    vl = *(const uint4*)(g_Al + abase + eoff);
                }
                *(uint4*)&sAh[lrow][seg*8] = vh;
                *(uint4*)&sAl[lrow][seg*8] = vl;
                *(uint4*)&sBh[lrow][seg*8] = *(const uint4*)(g_Bth + bbase + eoff);
                *(uint4*)&sBl[lrow][seg*8] = *(const uint4*)(g_Btl + bbase + eoff);
            }
        }
        __syncthreads();

#pragma unroll
        for (int q = 0; q < 2; q++) {
            uint32_t bhf[4][2], blf[4][2];
#pragma unroll
            for (int h = 0; h < 2; h++) {
                int rowB = wn*32 + h*16 + ((lane >> 4) << 3) + (lane & 7);
                int kb   = q*32 + (((lane >> 3) & 1) << 4);   // bytes
                uint32_t off = (uint32_t)(rowB*(SROW*2) + kb);
                uint32_t t[4];
                ldm4(t, bH + off);
                bhf[2*h][0] = t[0]; bhf[2*h][1] = t[1];
                bhf[2*h+1][0] = t[2]; bhf[2*h+1][1] = t[3];
                ldm4(t, bL + off);
                blf[2*h][0] = t[0]; blf[2*h][1] = t[1];
                blf[2*h+1][0] = t[2]; blf[2*h+1][1] = t[3];
            }
#pragma unroll
            for (int mt = 0; mt < 4; mt++) {
                int rowA = wm*64 + mt*16 + (lane & 15);
                int kb   = q*32 + ((lane >> 4) << 4);         // bytes
                uint32_t off = (uint32_t)(rowA*(SROW*2) + kb);
                uint32_t ah[4], al[4];
                ldm4(ah, aH + off);
                ldm4(al, aL + off);
#pragma unroll
                for (int nt = 0; nt < 4; nt++) {
                    mma16816(acc[mt][nt], ah, bhf[nt]);
                    mma16816(acc[mt][nt], ah, blf[nt]);
                    mma16816(acc[mt][nt], al, bhf[nt]);
                }
            }
        }
    }
    __syncthreads();

    // ---- epilogue: bias + relu (in registers), cross-warp row sums via smem ----
#pragma unroll
    for (int mt = 0; mt < 4; mt++) {
        float sL = 0.f, ssL = 0.f, sH = 0.f, ssH = 0.f;
#pragma unroll
        for (int nt = 0; nt < 4; nt++) {
            int gc = wn*32 + nt*8 + 2*(lane & 3);
            float b0 = sCb[gc], b1 = sCb[gc + 1];
            float v0 = fmaxf(acc[mt][nt][0] + b0, 0.f);
            float v1 = fmaxf(acc[mt][nt][1] + b1, 0.f);
            float v2 = fmaxf(acc[mt][nt][2] + b0, 0.f);
            float v3 = fmaxf(acc[mt][nt][3] + b1, 0.f);
            acc[mt][nt][0] = v0; acc[mt][nt][1] = v1;
            acc[mt][nt][2] = v2; acc[mt][nt][3] = v3;
            sL += v0 + v1; ssL = fmaf(v0, v0, fmaf(v1, v1, ssL));
            sH += v2 + v3; ssH = fmaf(v2, v2, fmaf(v3, v3, ssH));
        }
#pragma unroll
        for (int m = 1; m < 4; m <<= 1) {
            sL  += __shfl_xor_sync(0xffffffffu, sL,  m);
            ssL += __shfl_xor_sync(0xffffffffu, ssL, m);
            sH  += __shfl_xor_sync(0xffffffffu, sH,  m);
            ssH += __shfl_xor_sync(0xffffffffu, ssH, m);
        }
        if ((lane & 3) == 0) {
            int rl = wm*64 + mt*16 + (lane >> 2);
            sPart[rl][wn]     = make_float2(sL, ssL);
            sPart[rl + 8][wn] = make_float2(sH, ssH);
        }
    }
    __syncthreads();

#pragma unroll
    for (int mt = 0; mt < 4; mt++) {
        int rl = wm*64 + mt*16 + (lane >> 2);
        int rh = rl + 8;
        float2 p0 = sPart[rl][0], p1 = sPart[rl][1], p2 = sPart[rl][2], p3 = sPart[rl][3];
        float sA = p0.x + p1.x + p2.x + p3.x;
        float qA = p0.y + p1.y + p2.y + p3.y;
        p0 = sPart[rh][0]; p1 = sPart[rh][1]; p2 = sPart[rh][2]; p3 = sPart[rh][3];
        float sB = p0.x + p1.x + p2.x + p3.x;
        float qB = p0.y + p1.y + p2.y + p3.y;
        float mA = sA * (1.f/128.f);
        float rA = rsqrtf(qA * (1.f/128.f) - mA*mA + 1e-5f);
        float mB = sB * (1.f/128.f);
        float rB = rsqrtf(qB * (1.f/128.f) - mB*mB + 1e-5f);
        bool wlo = (row0 + rl < N), whi = (row0 + rh < N);
#pragma unroll
        for (int nt = 0; nt < 4; nt++) {
            int gc = wn*32 + nt*8 + 2*(lane & 3);
            float g0 = sGv[gc], g1 = sGv[gc+1], e0 = sBv[gc], e1 = sBv[gc+1];
            if (wlo) {
                float2 v;
                v.x = (acc[mt][nt][0] - mA)*rA*g0 + e0;
                v.y = (acc[mt][nt][1] - mA)*rA*g1 + e1;
                *(float2*)(out + (size_t)(row0 + rl)*DIM + gc) = v;
            }
            if (whi) {
                float2 v;
                v.x = (acc[mt][nt][2] - mB)*rB*g0 + e0;
                v.y = (acc[mt][nt][3] - mB)*rB*g1 + e1;
                *(float2*)(out + (size_t)(row0 + rh)*DIM + gc) = v;
            }
        }
    }
}

// ---------------- launch ----------------
extern "C" void kernel_launch(void* const* d_in, const int* in_sizes, int n_in,
                              void* d_out, int out_size) {
    const float* x     = (const float*)d_in[0];
    const void*  ei    = d_in[1];
    const void*  et    = d_in[2];
    const float* tim   = (const float*)d_in[3];
    const float* basis = (const float*)d_in[4];
    const float* comp  = (const float*)d_in[5];
    const float* root  = (const float*)d_in[6];
    const float* bias  = (const float*)d_in[7];
    const float* tpw   = (const float*)d_in[8];
    const float* tpb   = (const float*)d_in[9];
    const float* gamma = (const float*)d_in[10];
    const float* beta  = (const float*)d_in[11];
    float* out = (float*)d_out;

    int E = in_sizes[3];
    int N = in_sizes[0] / DIM;
    int nblk = (N + 1023) / 1024;

    k_detect  <<<1, 256>>>((const unsigned*)ei);
    k_zero_cnt<<<(N_NODES*NREL/4 + 255)/256, 256>>>();
    k_minmax  <<<1024, 256>>>(tim, E);
    k_wsum    <<<1024, 256>>>(tim, E);
    k_count   <<<(E + 255)/256, 256>>>(ei, et, E);
    k_scan1   <<<nblk, 1024>>>(N);
    k_scan2   <<<1, 32>>>(nblk);
    k_scan3   <<<(N + 255)/256, 256>>>(N, E);
    k_scatter <<<(E + 255)/256, 256>>>(ei, et, tim, E);
    {
        dim3 g((KTOT + 255)/256, DIM);
        k_makeBt<<<g, 256>>>(basis, root, tpw);
    }
    k_node    <<<(N + 7)/8, 256>>>(x, comp, N);
    k_gemm_hmma<<<(N + 127)/128, 256>>>(bias, tpb, gamma, beta, out, N);
}